// round 9
// baseline (speedup 1.0000x reference)
#include <cuda_runtime.h>
#include <cuda_fp16.h>
#include <cstdint>

typedef unsigned long long ull;

#define BB    2048
#define DIMD  200
#define NENT  100000
#define NENTP 100096
#define WELEM 8000000
#define KKD   40000
#define BNEPS 1e-5f

#define OFF_PRED 0LL
#define OFF_REG  204800000LL
#define OFF_T    204800005LL

#define NSPLIT 25

// ---------------- device scratch ----------------
__device__ float g_lhs  [BB*DIMD];
__device__ float g_relt [BB*DIMD];
__device__ float g_lhsn [BB*DIMD];
__device__ float g_colp [128*2*DIMD];
__device__ float g_s4p  [128*3];
__device__ float g_scale0[DIMD];
__device__ float g_shift0[DIMD];
__device__ float g_regsums[4];
__device__ float g_n4p  [400];
__device__ float g_wp   [625];
__device__ float g_h    [BB*DIMD];
__device__ float g_scale1[DIMD];
__device__ float g_shift1[DIMD];
// fp16 operands
__device__ __half g_Ef [(size_t)NENTP*256];   // E single fp16
__device__ __half g_hf [BB*256];              // h_n single fp16
__device__ __half g_Wt [(size_t)256*KKD];     // W^T single fp16
__device__ float g_hpA[(size_t)NSPLIT*BB*256];

// ---------------- helpers ----------------
__device__ __forceinline__ uint32_t smem_u32(const void* p) {
    uint32_t a;
    asm("{ .reg .u64 t; cvta.to.shared.u64 t, %1; cvt.u32.u64 %0, t; }" : "=r"(a) : "l"(p));
    return a;
}
__device__ __forceinline__ void cp16(uint32_t dst, const void* src) {
    asm volatile("cp.async.cg.shared.global [%0], [%1], 16;" :: "r"(dst), "l"(src));
}
#define CP_COMMIT() asm volatile("cp.async.commit_group;" ::: "memory")
#define CP_WAIT(n)  asm volatile("cp.async.wait_group %0;" :: "n"(n) : "memory")

__device__ __forceinline__ void ldsm_x4(uint32_t& r0, uint32_t& r1, uint32_t& r2, uint32_t& r3, uint32_t addr) {
    asm volatile("ldmatrix.sync.aligned.m8n8.x4.shared.b16 {%0,%1,%2,%3}, [%4];"
        : "=r"(r0), "=r"(r1), "=r"(r2), "=r"(r3) : "r"(addr));
}
__device__ __forceinline__ void mma16816(float* c, const uint32_t* a, uint32_t b0, uint32_t b1) {
    asm volatile("mma.sync.aligned.m16n8k16.row.col.f32.f16.f16.f32 "
        "{%0,%1,%2,%3}, {%4,%5,%6,%7}, {%8,%9}, {%0,%1,%2,%3};"
        : "+f"(c[0]), "+f"(c[1]), "+f"(c[2]), "+f"(c[3])
        : "r"(a[0]), "r"(a[1]), "r"(a[2]), "r"(a[3]), "r"(b0), "r"(b1));
}
#define SWZ128(x) ((x) ^ (((x) >> 3) & 0x70))

__device__ __forceinline__ float blockReduce256(float v, float* red) {
    int t = threadIdx.x;
    red[t] = v; __syncthreads();
#pragma unroll
    for (int s = 128; s > 0; s >>= 1) {
        if (t < s) red[t] += red[t + s];
        __syncthreads();
    }
    float r = red[0]; __syncthreads();
    return r;
}

// ---------------- K1: gather + BN0 partials + norm4 partials ----------------
__global__ void k_gather(const int* __restrict__ x,
                         const float* __restrict__ E,
                         const float* __restrict__ R,
                         const float* __restrict__ RnT,
                         const float* __restrict__ T)
{
    __shared__ float red[256];
    int t = threadIdx.x;
    int d = t;
    float cs = 0.f, cq = 0.f, s_rt = 0.f, s_rn = 0.f, s_rh = 0.f;
    if (d < DIMD) {
#pragma unroll 4
        for (int i = 0; i < 16; i++) {
            int b = blockIdx.x * 16 + i;
            int i0 = x[b*4+0], i1 = x[b*4+1], i2 = x[b*4+2], i3 = x[b*4+3];
            float l  = E[(size_t)i0*DIMD + d];
            float rt = R[(size_t)i1*DIMD + d] * T[(size_t)i3*DIMD + d];
            float rn = RnT[(size_t)i1*DIMD + d];
            float rh = E[(size_t)i2*DIMD + d];
            g_lhs [b*DIMD + d] = l;
            g_relt[b*DIMD + d] = rt;
            cs += l; cq += l*l;
            float a = rt*rt;  s_rt += a*a;
            float bq = rn*rn; s_rn += bq*bq;
            float cc = rh*rh; s_rh += cc*cc;
        }
        g_colp[blockIdx.x*2*DIMD + d]        = cs;
        g_colp[blockIdx.x*2*DIMD + DIMD + d] = cq;
    }
    float r0 = blockReduce256(s_rt, red);
    float r1 = blockReduce256(s_rn, red);
    float r2 = blockReduce256(s_rh, red);
    if (t == 0) {
        g_s4p[blockIdx.x*3 + 0] = r0;
        g_s4p[blockIdx.x*3 + 1] = r1;
        g_s4p[blockIdx.x*3 + 2] = r2;
    }
}

// ---------------- K2: BN0 stats + reg sums ----------------
__global__ void k_stats0(const float* __restrict__ gamma0, const float* __restrict__ beta0)
{
    int t = threadIdx.x;
    if (t < DIMD) {
        float s = 0.f, sq = 0.f;
        for (int k = 0; k < 128; k++) {
            s  += g_colp[k*2*DIMD + t];
            sq += g_colp[k*2*DIMD + DIMD + t];
        }
        float mu  = s  * (1.f/2048.f);
        float var = sq * (1.f/2048.f) - mu*mu;
        float rs  = rsqrtf(var + BNEPS);
        float sc  = rs * gamma0[t];
        g_scale0[t] = sc;
        g_shift0[t] = beta0[t] - mu*sc;
    } else if (t < DIMD + 3) {
        int j = t - DIMD;
        float s = 0.f;
        for (int k = 0; k < 128; k++) s += g_s4p[k*3 + j];
        g_regsums[j + 1] = s;
    }
}

// ---------------- K3: norm4(lhs_n) + materialize lhs_n ----------------
__global__ void k_norm4L()
{
    __shared__ float red[256];
    int t = threadIdx.x;
    float pl = 0.f;
    int base = blockIdx.x * 1024;
#pragma unroll
    for (int j = 0; j < 4; j++) {
        int i = base + t + 256*j;
        if (i < BB*DIMD) {
            int d = i % DIMD;
            float v = g_lhs[i] * g_scale0[d] + g_shift0[d];
            g_lhsn[i] = v;
            float v2 = v*v; pl += v2*v2;
        }
    }
    float rl = blockReduce256(pl, red);
    if (t == 0) g_n4p[blockIdx.x] = rl;
}

// ---------------- K4: W -> Wt (transposed fp16, e padded) + norm4(W) partials ----------------
#define SPLITW_SMEM (64*DIMD*4 + 1024)
__global__ void k_splitW(const float* __restrict__ W)
{
    extern __shared__ char swraw[];
    float* sm  = (float*)swraw;                 // 64 x 200
    float* red = (float*)(swraw + 64*DIMD*4);   // 256
    int t = threadIdx.x;
    int kd0 = blockIdx.x * 64;
    float pw = 0.f;
    for (int i = t; i < 64*DIMD; i += 256) {
        float v = W[(size_t)kd0*DIMD + i];
        sm[i] = v;
        float v2 = v*v; pw += v2*v2;
    }
    __syncthreads();
    for (int idx = t; idx < 256*64; idx += 256) {
        int e = idx >> 6, kd = idx & 63;
        float v = (e < DIMD) ? sm[kd*DIMD + e] : 0.f;
        g_Wt[(size_t)e*KKD + kd0 + kd] = __float2half_rn(v);
    }
    float r = blockReduce256(pw, red);
    if (t == 0) g_wp[blockIdx.x] = r;
}

// ---------------- K5: write reg[5] ----------------
__global__ void k_finreg(float* __restrict__ out)
{
    __shared__ float red[256];
    int t = threadIdx.x;
    float a = 0.f, b = 0.f;
    for (int i = t; i < 400; i += 256) a += g_n4p[i];
    for (int i = t; i < 625; i += 256) b += g_wp[i];
    float sl = blockReduce256(a, red);
    float sw = blockReduce256(b, red);
    if (t == 0) {
        out[OFF_REG + 0] = powf(sl,           0.25f);
        out[OFF_REG + 1] = powf(g_regsums[1], 0.25f);
        out[OFF_REG + 2] = powf(g_regsums[2], 0.25f);
        out[OFF_REG + 3] = powf(g_regsums[3], 0.25f);
        out[OFF_REG + 4] = powf(sw,           0.25f);
    }
}

// ---------------- K6: GEMM-A fused (A' computed in-kernel) ----------------
// CTA: 128 b x 256 n(e, padded), K-slice 1600 (25 chunks of 64), 512 thr.
// 16 warps = 4b x 4n; warp 32b x 64n. smem: Abuf 2x16K @0, Wbuf 2x32K @32768,
// sl fp32 128x200 @98304, sr fp32 128x8 @200704.
#define SMEM_GA (204800 + 1024)
__global__ void __launch_bounds__(512, 1) k_gemmA_mma()
{
    extern __shared__ char smrawA[];
    uint32_t base0 = smem_u32(smrawA);
    uint32_t base  = (base0 + 1023) & ~1023u;
    char* cbase = smrawA + (base - base0);
    float* sl = (float*)(cbase + 98304);
    float* sr = (float*)(cbase + 200704);

    int t = threadIdx.x;
    int lane = t & 31, wid = t >> 5;
    int wb = wid >> 2, wn = wid & 3;
    int b0  = blockIdx.x * 128;
    int kd0 = blockIdx.y * 1600;
    int k0  = blockIdx.y * 8;

    // issue W chunk 0
    {
        uint32_t st = base + 32768;
#pragma unroll
        for (int j = 0; j < 4; j++) {
            int idx = t + 512*j;
            int row = idx >> 3, seg = idx & 7;
            cp16(st + SWZ128(row*128 + seg*16), g_Wt + (size_t)row*KKD + kd0 + seg*8);
        }
        CP_COMMIT();
    }
    // load sr (128x8), sl (128x200)
    for (int i = t; i < 128*8; i += 512)
        sr[i] = g_relt[(b0 + (i >> 3))*DIMD + k0 + (i & 7)];
    for (int i = t; i < 128*DIMD; i += 512)
        sl[i] = g_lhsn[(b0 + i/DIMD)*DIMD + i%DIMD];
    __syncthreads();

    // fill A chunk 0 into buf 0
    {
        char* ab = cbase;
#pragma unroll
        for (int j = 0; j < 8; j++) {
            int h2 = t + 512*j;
            int row = h2 >> 5, cp_ = h2 & 31;
            int col = cp_ * 2;
            int kd  = col;                 // chunk 0
            int k1 = kd/200,  d1 = kd  - k1*200;
            int k2 = (kd+1)/200, d2 = kd+1 - k2*200;
            float v0 = sr[row*8 + k1] * sl[row*200 + d1];
            float v1 = sr[row*8 + k2] * sl[row*200 + d2];
            *(__half2*)(ab + SWZ128(row*128 + col*2)) = __floats2half2_rn(v0, v1);
        }
    }

    float acc[2][8][4];
#pragma unroll
    for (int i = 0; i < 2; i++)
#pragma unroll
        for (int j = 0; j < 8; j++)
#pragma unroll
            for (int q = 0; q < 4; q++) acc[i][j][q] = 0.f;

    for (int c = 0; c < 25; c++) {
        CP_WAIT(0);
        __syncthreads();   // W[c] visible; A[c] visible; mma c-1 done everywhere

        if (c + 1 < 25) {  // issue W[c+1] (buffer's last reader mma c-1 is done)
            int kc = (c+1)*64;
            uint32_t st = base + 32768 + ((c+1)&1)*32768;
#pragma unroll
            for (int j = 0; j < 4; j++) {
                int idx = t + 512*j;
                int row = idx >> 3, seg = idx & 7;
                cp16(st + SWZ128(row*128 + seg*16), g_Wt + (size_t)row*KKD + kd0 + kc + seg*8);
            }
            CP_COMMIT();
        }

        // mma on buffers c&1
        {
            uint32_t ab  = base + (c&1)*16384;
            uint32_t wbf = base + 32768 + (c&1)*32768;
            int rl = lane & 15;
            for (int ks = 0; ks < 4; ks++) {
                int ch = 2*ks + (lane >> 4);
                uint32_t a[2][4];
#pragma unroll
                for (int mi = 0; mi < 2; mi++) {
                    int row = wb*32 + mi*16 + rl;
                    ldsm_x4(a[mi][0], a[mi][1], a[mi][2], a[mi][3], ab + SWZ128(row*128 + ch*16));
                }
                uint32_t bf[8][2];
#pragma unroll
                for (int nj = 0; nj < 4; nj++) {
                    uint32_t r0, r1, r2, r3;
                    int row = wn*64 + nj*16 + rl;
                    ldsm_x4(r0, r1, r2, r3, wbf + SWZ128(row*128 + ch*16));
                    bf[nj*2+0][0] = r0; bf[nj*2+0][1] = r2;
                    bf[nj*2+1][0] = r1; bf[nj*2+1][1] = r3;
                }
#pragma unroll
                for (int mi = 0; mi < 2; mi++)
#pragma unroll
                    for (int ni = 0; ni < 8; ni++)
                        mma16816(acc[mi][ni], a[mi], bf[ni][0], bf[ni][1]);
            }
        }

        // fill A[c+1] into the other buffer (its last reader, mma c-1, is done)
        if (c + 1 < 25) {
            char* ab = cbase + ((c+1)&1)*16384;
            int kbase = (c+1)*64;
#pragma unroll
            for (int j = 0; j < 8; j++) {
                int h2 = t + 512*j;
                int row = h2 >> 5, cp_ = h2 & 31;
                int col = cp_ * 2;
                int kd  = kbase + col;
                int k1 = kd/200,  d1 = kd  - k1*200;
                int k2 = (kd+1)/200, d2 = kd+1 - k2*200;
                float v0 = sr[row*8 + k1] * sl[row*200 + d1];
                float v1 = sr[row*8 + k2] * sl[row*200 + d2];
                *(__half2*)(ab + SWZ128(row*128 + col*2)) = __floats2half2_rn(v0, v1);
            }
        }
    }

    float* dst = g_hpA + (size_t)blockIdx.y * (BB*256);
    int g = lane >> 2, c2 = (lane & 3)*2;
#pragma unroll
    for (int mi = 0; mi < 2; mi++) {
#pragma unroll
        for (int ni = 0; ni < 8; ni++) {
            int col = wn*64 + ni*8 + c2;
            if (col < DIMD) {
                size_t r0 = (size_t)(b0 + wb*32 + mi*16 + g) * 256 + col;
                *(float2*)(dst + r0)         = make_float2(acc[mi][ni][0], acc[mi][ni][1]);
                *(float2*)(dst + r0 + 8*256) = make_float2(acc[mi][ni][2], acc[mi][ni][3]);
            }
        }
    }
}

// ---------------- K7: reduce k-split partials ----------------
__global__ void k_redhA()
{
    int i = blockIdx.x*256 + threadIdx.x;
    if (i < BB*DIMD) {
        int b = i / DIMD, n = i - b*DIMD;
        float s = 0.f;
#pragma unroll
        for (int ks = 0; ks < NSPLIT; ks++)
            s += g_hpA[(size_t)ks*(BB*256) + (size_t)b*256 + n];
        g_h[i] = s;
    }
}

// ---------------- K8: BN1 stats ----------------
__global__ void k_stats1(const float* __restrict__ gamma1, const float* __restrict__ beta1)
{
    __shared__ float r0[256];
    int e = blockIdx.x, t = threadIdx.x;
    float s = 0.f, sq = 0.f;
    for (int b = t; b < BB; b += 256) {
        float v = g_h[b*DIMD + e];
        s += v; sq += v*v;
    }
    float ts = blockReduce256(s, r0);
    float tq = blockReduce256(sq, r0);
    if (t == 0) {
        float mu  = ts * (1.f/2048.f);
        float var = tq * (1.f/2048.f) - mu*mu;
        float rs  = rsqrtf(var + BNEPS);
        float sc  = rs * gamma1[e];
        g_scale1[e] = sc;
        g_shift1[e] = beta1[e] - mu*sc;
    }
}

// ---------------- K9: E -> fp16 single (padded) ----------------
__global__ void k_splitE(const float* __restrict__ E)
{
    int r = blockIdx.x;
    int c = threadIdx.x * 2;
    float v0 = 0.f, v1 = 0.f;
    if (r < NENT) {
        if (c < DIMD)     v0 = E[(size_t)r*DIMD + c];
        if (c + 1 < DIMD) v1 = E[(size_t)r*DIMD + c + 1];
    }
    *(__half2*)&g_Ef[(size_t)r*256 + c] = __floats2half2_rn(v0, v1);
}

// ---------------- K10: BN1 apply, h_n -> single fp16 ----------------
__global__ void k_hconv()
{
    int b = blockIdx.x;
    int c = threadIdx.x * 2;
    float v0 = 0.f, v1 = 0.f;
    if (c < DIMD)     v0 = g_h[b*DIMD + c]     * g_scale1[c]     + g_shift1[c];
    if (c + 1 < DIMD) v1 = g_h[b*DIMD + c + 1] * g_scale1[c + 1] + g_shift1[c + 1];
    *(__half2*)&g_hf[(size_t)b*256 + c] = __floats2half2_rn(v0, v1);
}

// ---------------- K11: GEMM-B via mma.sync fp16, single pass ----------------
// CTA: 256 b x 128 n, 512 thr. 16 warps = 4b x 4n; warp 64b x 32n.
// 4 K-chunks of 64. h @0 (32KB), E @32768 (16KB). b fastest in grid -> E L2 reuse.
#define GB_STG 49152
#define SMEM_GB (2*GB_STG + 1024)
__global__ void __launch_bounds__(512, 1) k_gemmB_mma(float* __restrict__ out)
{
    extern __shared__ char smrawB[];
    uint32_t base = (smem_u32(smrawB) + 1023) & ~1023u;

    int t = threadIdx.x;
    int lane = t & 31, wid = t >> 5;
    int wb = wid >> 2, wn = wid & 3;
    int b0 = blockIdx.x * 256;
    int n0 = blockIdx.y * 128;

    float acc[4][4][4];
#pragma unroll
    for (int i = 0; i < 4; i++)
#pragma unroll
        for (int j = 0; j < 4; j++)
#pragma unroll
            for (int q = 0; q < 4; q++) acc[i][j][q] = 0.f;

    {
        uint32_t st = base;
#pragma unroll
        for (int j = 0; j < 4; j++) {
            int idx = t + 512*j;
            int row = idx >> 3, seg = idx & 7;
            cp16(st + SWZ128(row*128 + seg*16), g_hf + (size_t)(b0 + row)*256 + seg*8);
        }
#pragma unroll
        for (int j = 0; j < 2; j++) {
            int idx = t + 512*j;
            int row = idx >> 3, seg = idx & 7;
            cp16(st + 32768 + SWZ128(row*128 + seg*16), g_Ef + (size_t)(n0 + row)*256 + seg*8);
        }
        CP_COMMIT();
    }

    for (int c = 0; c < 4; c++) {
        if (c + 1 < 4) {
            int kc = (c+1)*64;
            uint32_t st = base + ((c+1)&1)*GB_STG;
#pragma unroll
            for (int j = 0; j < 4; j++) {
                int idx = t + 512*j;
                int row = idx >> 3, seg = idx & 7;
                cp16(st + SWZ128(row*128 + seg*16), g_hf + (size_t)(b0 + row)*256 + kc + seg*8);
            }
#pragma unroll
            for (int j = 0; j < 2; j++) {
                int idx = t + 512*j;
                int row = idx >> 3, seg = idx & 7;
                cp16(st + 32768 + SWZ128(row*128 + seg*16), g_Ef + (size_t)(n0 + row)*256 + kc + seg*8);
            }
            CP_COMMIT();
            CP_WAIT(1);
        } else {
            CP_WAIT(0);
        }
        __syncthreads();

        uint32_t st = base + (c&1)*GB_STG;
        int nst = (c == 3) ? 1 : 4;
        int rl = lane & 15;
        for (int ks = 0; ks < nst; ks++) {
            int ch = 2*ks + (lane >> 4);
            uint32_t a[4][4];
#pragma unroll
            for (int mi = 0; mi < 4; mi++) {
                int row = wb*64 + mi*16 + rl;
                ldsm_x4(a[mi][0], a[mi][1], a[mi][2], a[mi][3], st + SWZ128(row*128 + ch*16));
            }
            uint32_t bf[4][2];
#pragma unroll
            for (int nj = 0; nj < 2; nj++) {
                uint32_t r0, r1, r2, r3;
                int row = wn*32 + nj*16 + rl;
                ldsm_x4(r0, r1, r2, r3, st + 32768 + SWZ128(row*128 + ch*16));
                bf[nj*2+0][0] = r0; bf[nj*2+0][1] = r2;
                bf[nj*2+1][0] = r1; bf[nj*2+1][1] = r3;
            }
#pragma unroll
            for (int mi = 0; mi < 4; mi++)
#pragma unroll
                for (int ni = 0; ni < 4; ni++)
                    mma16816(acc[mi][ni], a[mi], bf[ni][0], bf[ni][1]);
        }
        __syncthreads();
    }

    int g = lane >> 2, c2 = (lane & 3)*2;
#pragma unroll
    for (int mi = 0; mi < 4; mi++) {
#pragma unroll
        for (int ni = 0; ni < 4; ni++) {
            int col = n0 + wn*32 + ni*8 + c2;
            if (col < NENT) {
                size_t r0 = (size_t)(b0 + wb*64 + mi*16 + g) * NENT + col;
                size_t r1 = r0 + (size_t)8 * NENT;
                *(float2*)(out + r0) = make_float2(acc[mi][ni][0], acc[mi][ni][1]);
                *(float2*)(out + r1) = make_float2(acc[mi][ni][2], acc[mi][ni][3]);
            }
        }
    }
}

// ---------------- launch ----------------
extern "C" void kernel_launch(void* const* d_in, const int* in_sizes, int n_in,
                              void* d_out, int out_size)
{
    const int*   x   = (const int*)d_in[0];
    const float* E   = (const float*)d_in[1];
    const float* R   = (const float*)d_in[2];
    const float* RnT = (const float*)d_in[3];
    const float* T   = (const float*)d_in[4];
    const float* W   = (const float*)d_in[5];
    const float* g0  = (const float*)d_in[6];
    const float* be0 = (const float*)d_in[7];
    const float* g1  = (const float*)d_in[8];
    const float* be1 = (const float*)d_in[9];
    float* out = (float*)d_out;

    cudaFuncSetAttribute(k_splitW,    cudaFuncAttributeMaxDynamicSharedMemorySize, SPLITW_SMEM);
    cudaFuncSetAttribute(k_gemmA_mma, cudaFuncAttributeMaxDynamicSharedMemorySize, SMEM_GA);
    cudaFuncSetAttribute(k_gemmB_mma, cudaFuncAttributeMaxDynamicSharedMemorySize, SMEM_GB);

    k_gather<<<128, 256>>>(x, E, R, RnT, T);
    k_stats0<<<1, 256>>>(g0, be0);
    k_norm4L<<<400, 256>>>();
    k_splitW<<<625, 256, SPLITW_SMEM>>>(W);
    k_finreg<<<1, 256>>>(out);
    k_splitE<<<NENTP, 128>>>(E);
    k_gemmA_mma<<<dim3(16, NSPLIT), 512, SMEM_GA>>>();
    k_redhA<<<1600, 256>>>();
    k_stats1<<<200, 256>>>(g1, be1);
    k_hconv<<<BB, 128>>>();
    k_gemmB_mma<<<dim3(8, 782), 512, SMEM_GB>>>(out);
    cudaMemcpyAsync(out + OFF_T, T, 80000 * sizeof(float), cudaMemcpyDeviceToDevice);
}